// round 4
// baseline (speedup 1.0000x reference)
#include <cuda_runtime.h>
#include <cstdint>
#include <mma.h>

using namespace nvcuda;

#define B_  4
#define T_  4096
#define D_  1024
#define N_  2048
#define L_  768
#define H_  16
#define DH  64
#define NSEG 8
#define STAGES 3

// ---------------- scratch (static device globals; no allocation) ----------------
__device__ float g_nx1[(size_t)B_ * T_ * D_];
__device__ float g_nx2[(size_t)B_ * N_ * L_];
__device__ float g_q  [(size_t)B_ * T_ * D_];
__device__ float g_k  [(size_t)B_ * N_ * D_];
__device__ float g_v  [(size_t)B_ * N_ * D_];
__device__ float g_ap [(size_t)NSEG * B_ * H_ * DH * DH];
__device__ float g_attn[(size_t)B_ * H_ * DH * DH];

// ---------------- LayerNorm ----------------
__global__ void __launch_bounds__(256) ln_kernel(const float* __restrict__ x,
                                                 const float* __restrict__ g,
                                                 const float* __restrict__ bb,
                                                 float* __restrict__ out, int D) {
    int row = blockIdx.x;
    const float* xr = x + (size_t)row * D;
    int cnt = D >> 8;
    float v[4];
    float s = 0.f, s2 = 0.f;
    for (int i = 0; i < cnt; i++) {
        v[i] = xr[threadIdx.x + (i << 8)];
        s += v[i];
        s2 += v[i] * v[i];
    }
    #pragma unroll
    for (int o = 16; o; o >>= 1) {
        s  += __shfl_xor_sync(0xffffffffu, s, o);
        s2 += __shfl_xor_sync(0xffffffffu, s2, o);
    }
    __shared__ float sa[8], sb[8];
    int w = threadIdx.x >> 5, lane = threadIdx.x & 31;
    if (lane == 0) { sa[w] = s; sb[w] = s2; }
    __syncthreads();
    if (w == 0) {
        s  = (lane < 8) ? sa[lane] : 0.f;
        s2 = (lane < 8) ? sb[lane] : 0.f;
        #pragma unroll
        for (int o = 4; o; o >>= 1) {
            s  += __shfl_xor_sync(0xffffffffu, s, o);
            s2 += __shfl_xor_sync(0xffffffffu, s2, o);
        }
        if (lane == 0) { sa[0] = s; sb[0] = s2; }
    }
    __syncthreads();
    float invD = 1.f / (float)D;
    float mu  = sa[0] * invD;
    float var = sb[0] * invD - mu * mu;
    float inv = rsqrtf(var + 1e-5f);
    float* orow = out + (size_t)row * D;
    for (int i = 0; i < cnt; i++) {
        int c = threadIdx.x + (i << 8);
        orow[c] = (v[i] - mu) * inv * g[c] + bb[c];
    }
}

// ---------------- cp.async helpers ----------------
__device__ __forceinline__ void cp16(float* smem_dst, const float* gsrc) {
    unsigned int s = (unsigned int)__cvta_generic_to_shared(smem_dst);
    asm volatile("cp.async.cg.shared.global [%0], [%1], 16;\n" :: "r"(s), "l"(gsrc));
}
__device__ __forceinline__ void cp_commit() {
    asm volatile("cp.async.commit_group;\n" ::);
}
__device__ __forceinline__ void cp_wait1() {
    asm volatile("cp.async.wait_group 1;\n" ::);
}

// ---------------- GEMM: C[M,N] = A[M,K] @ W[K,N], tf32 wmma, 3-stage cp.async ----------------
// BM=128 BN=128 BK=32, 256 threads (8 warps in 2x4), warp tile 64x32.
// Per-stage smem: A 128x40 floats (20480B) + B 32x136 floats (17408B) = 37888B; x3 = 113664B.
#define A_PITCH 40
#define B_PITCH 136
#define STG_FLOATS 9472   // 128*40 + 32*136

__global__ void __launch_bounds__(256) gemm_tf32(const float* __restrict__ A,
                                                 const float* __restrict__ W,
                                                 float* __restrict__ C,
                                                 int M, int N, int K) {
    extern __shared__ float sm[];
    int bm = blockIdx.y * 128, bn = blockIdx.x * 128;
    int tid = threadIdx.x;
    int wid = tid >> 5;
    int wm = (wid >> 2) * 64, wn = (wid & 3) * 32;

    // per-thread load coords (fixed)
    int ar = tid >> 3,  ac = (tid & 7) << 2;     // A: 32 rows per 256-thread pass
    int br = tid >> 5,  bc = (tid & 31) << 2;    // B: 8 rows per pass

    wmma::fragment<wmma::accumulator, 16, 16, 8, float> acc[4][2];
    #pragma unroll
    for (int i = 0; i < 4; i++)
        #pragma unroll
        for (int j = 0; j < 2; j++) wmma::fill_fragment(acc[i][j], 0.f);

    int KT = K >> 5;

    // prologue: issue STAGES-1 stages
    #pragma unroll
    for (int s = 0; s < STAGES - 1; s++) {
        float* as = sm + s * STG_FLOATS;
        float* bs = as + 128 * A_PITCH;
        int k0 = s << 5;
        #pragma unroll
        for (int i = 0; i < 4; i++) {
            int r = ar + i * 32;
            cp16(as + r * A_PITCH + ac, A + (size_t)(bm + r) * K + k0 + ac);
        }
        #pragma unroll
        for (int i = 0; i < 4; i++) {
            int r = br + i * 8;
            cp16(bs + r * B_PITCH + bc, W + (size_t)(k0 + r) * N + bn + bc);
        }
        cp_commit();
    }

    for (int kt = 0; kt < KT; kt++) {
        cp_wait1();
        __syncthreads();

        // issue load for stage kt+STAGES-1
        int ldk = kt + STAGES - 1;
        if (ldk < KT) {
            int s = ldk % STAGES;
            float* as = sm + s * STG_FLOATS;
            float* bs = as + 128 * A_PITCH;
            int k0 = ldk << 5;
            #pragma unroll
            for (int i = 0; i < 4; i++) {
                int r = ar + i * 32;
                cp16(as + r * A_PITCH + ac, A + (size_t)(bm + r) * K + k0 + ac);
            }
            #pragma unroll
            for (int i = 0; i < 4; i++) {
                int r = br + i * 8;
                cp16(bs + r * B_PITCH + bc, W + (size_t)(k0 + r) * N + bn + bc);
            }
        }
        cp_commit();

        // compute stage kt
        int s = kt % STAGES;
        float* as = sm + s * STG_FLOATS;
        float* bs = as + 128 * A_PITCH;
        #pragma unroll
        for (int kk = 0; kk < 32; kk += 8) {
            wmma::fragment<wmma::matrix_a, 16, 16, 8, wmma::precision::tf32, wmma::row_major> af[4];
            wmma::fragment<wmma::matrix_b, 16, 16, 8, wmma::precision::tf32, wmma::row_major> bf[2];
            #pragma unroll
            for (int i = 0; i < 4; i++) {
                wmma::load_matrix_sync(af[i], as + (wm + 16 * i) * A_PITCH + kk, A_PITCH);
                #pragma unroll
                for (int t = 0; t < af[i].num_elements; t++)
                    af[i].x[t] = wmma::__float_to_tf32(af[i].x[t]);
            }
            #pragma unroll
            for (int j = 0; j < 2; j++) {
                wmma::load_matrix_sync(bf[j], bs + kk * B_PITCH + wn + 16 * j, B_PITCH);
                #pragma unroll
                for (int t = 0; t < bf[j].num_elements; t++)
                    bf[j].x[t] = wmma::__float_to_tf32(bf[j].x[t]);
            }
            #pragma unroll
            for (int i = 0; i < 4; i++)
                #pragma unroll
                for (int j = 0; j < 2; j++)
                    wmma::mma_sync(acc[i][j], af[i], bf[j], acc[i][j]);
        }
        __syncthreads();
    }

    #pragma unroll
    for (int i = 0; i < 4; i++)
        #pragma unroll
        for (int j = 0; j < 2; j++)
            wmma::store_matrix_sync(C + (size_t)(bm + wm + 16 * i) * N + bn + wn + 16 * j,
                                    acc[i][j], N, wmma::mem_row_major);
}

// ---------------- bias + per-head softmax over 64-chunks (in place) ----------------
__global__ void __launch_bounds__(512) softmax64_kernel(float* __restrict__ buf,
                                                        const float* __restrict__ bias) {
    int row = blockIdx.x;
    int w = threadIdx.x >> 5, lane = threadIdx.x & 31;
    float* p = buf + (size_t)row * 1024 + w * 64;
    float a = p[lane]      + bias[w * 64 + lane];
    float b = p[lane + 32] + bias[w * 64 + lane + 32];
    float m = fmaxf(a, b);
    #pragma unroll
    for (int o = 16; o; o >>= 1) m = fmaxf(m, __shfl_xor_sync(0xffffffffu, m, o));
    float ea = __expf(a - m), eb = __expf(b - m);
    float s = ea + eb;
    #pragma unroll
    for (int o = 16; o; o >>= 1) s += __shfl_xor_sync(0xffffffffu, s, o);
    float inv = 1.f / s;
    p[lane]      = ea * inv;
    p[lane + 32] = eb * inv;
}

// ---------------- bias add (V) ----------------
__global__ void __launch_bounds__(256) addbias_kernel(float* __restrict__ v,
                                                      const float* __restrict__ b) {
    float* p = v + (size_t)blockIdx.x * 1024;
    #pragma unroll
    for (int i = 0; i < 4; i++) {
        int c = threadIdx.x + (i << 8);
        p[c] += b[c];
    }
}

// ---------------- attn partials ----------------
__global__ void __launch_bounds__(256) attn_part_kernel(const float* __restrict__ k,
                                                        const float* __restrict__ v,
                                                        float* __restrict__ ap) {
    __shared__ float ks[32][68], vs[32][68];
    int bh = blockIdx.x;
    int b = bh >> 4, h = bh & 15;
    int seg = blockIdx.y;
    int tid = threadIdx.x;
    int d0 = (tid >> 4) << 2, l0 = (tid & 15) << 2;
    float acc[4][4];
    #pragma unroll
    for (int i = 0; i < 4; i++)
        #pragma unroll
        for (int j = 0; j < 4; j++) acc[i][j] = 0.f;

    const float* kb = k + (size_t)(b * N_) * D_ + h * 64;
    const float* vb = v + (size_t)(b * N_) * D_ + h * 64;
    int nend = seg * 256 + 256;
    for (int n0 = seg * 256; n0 < nend; n0 += 32) {
        #pragma unroll
        for (int i = 0; i < 2; i++) {
            int idx = tid + i * 256;
            int r = idx >> 4, c = (idx & 15) << 2;
            *(float4*)&ks[r][c] = *(const float4*)(kb + (size_t)(n0 + r) * D_ + c);
            *(float4*)&vs[r][c] = *(const float4*)(vb + (size_t)(n0 + r) * D_ + c);
        }
        __syncthreads();
        #pragma unroll 8
        for (int n = 0; n < 32; n++) {
            float kr[4], vr[4];
            #pragma unroll
            for (int i = 0; i < 4; i++) { kr[i] = ks[n][d0 + i]; vr[i] = vs[n][l0 + i]; }
            #pragma unroll
            for (int i = 0; i < 4; i++)
                #pragma unroll
                for (int j = 0; j < 4; j++) acc[i][j] += kr[i] * vr[j];
        }
        __syncthreads();
    }
    float* dst = ap + ((size_t)seg * (B_ * H_) + bh) * 4096;
    #pragma unroll
    for (int i = 0; i < 4; i++)
        #pragma unroll
        for (int j = 0; j < 4; j++) dst[(d0 + i) * 64 + l0 + j] = acc[i][j];
}

__global__ void __launch_bounds__(256) attn_reduce_kernel(const float* __restrict__ ap,
                                                          float* __restrict__ attn) {
    int i = blockIdx.x * blockDim.x + threadIdx.x;
    #pragma unroll
    for (int r = 0; r < 4; r++) {
        int j = i + r * 65536;
        float s = 0.f;
        #pragma unroll
        for (int sg = 0; sg < NSEG; sg++) s += ap[(size_t)sg * (B_ * H_ * 4096) + j];
        attn[j] = s;
    }
}

// ---------------- final: out = Ch + bh + q @ attn ----------------
__global__ void __launch_bounds__(256) final_kernel(const float* __restrict__ Ch,
                                                    const float* __restrict__ bh,
                                                    const float* __restrict__ q,
                                                    const float* __restrict__ attn,
                                                    float* __restrict__ out) {
    __shared__ float sA[64][64];
    __shared__ float sQ[64][68];
    int t0 = blockIdx.x * 64, h = blockIdx.y, b = blockIdx.z;
    int tid = threadIdx.x;
    const float* ap = attn + (size_t)(b * H_ + h) * 4096;
    #pragma unroll
    for (int i = 0; i < 4; i++) {
        int idx = tid + i * 256;
        int r = idx >> 4, c = (idx & 15) << 2;
        *(float4*)&sA[r][c] = *(const float4*)(ap + r * 64 + c);
    }
    #pragma unroll
    for (int i = 0; i < 4; i++) {
        int idx = tid + i * 256;
        int r = idx >> 4, c = (idx & 15) << 2;
        *(float4*)&sQ[r][c] = *(const float4*)(q + (size_t)(b * T_ + t0 + r) * D_ + h * 64 + c);
    }
    __syncthreads();
    int tl = tid >> 2, l0 = (tid & 3) << 4;
    float accv[16];
    #pragma unroll
    for (int j = 0; j < 16; j++) accv[j] = 0.f;
    #pragma unroll 4
    for (int d = 0; d < 64; d++) {
        float qd = sQ[tl][d];
        #pragma unroll
        for (int jj = 0; jj < 4; jj++) {
            float4 a4 = *(const float4*)&sA[d][l0 + jj * 4];
            accv[jj * 4 + 0] += qd * a4.x;
            accv[jj * 4 + 1] += qd * a4.y;
            accv[jj * 4 + 2] += qd * a4.z;
            accv[jj * 4 + 3] += qd * a4.w;
        }
    }
    size_t base = (size_t)(b * T_ + t0 + tl) * D_ + h * 64 + l0;
    #pragma unroll
    for (int j = 0; j < 16; j++)
        out[base + j] = Ch[base + j] + bh[h * 64 + l0 + j] + accv[j];
}

// ---------------- launch ----------------
extern "C" void kernel_launch(void* const* d_in, const int* in_sizes, int n_in,
                              void* d_out, int out_size) {
    const float* x1 = (const float*)d_in[0];
    const float* x2 = (const float*)d_in[1];
    const float* Wq = (const float*)d_in[2];
    const float* bq = (const float*)d_in[3];
    const float* Wk = (const float*)d_in[4];
    const float* bk = (const float*)d_in[5];
    const float* Wv = (const float*)d_in[6];
    const float* bv = (const float*)d_in[7];
    const float* Wh = (const float*)d_in[8];
    const float* bh = (const float*)d_in[9];
    const float* g1 = (const float*)d_in[10];
    const float* b1 = (const float*)d_in[11];
    const float* g2 = (const float*)d_in[12];
    const float* b2 = (const float*)d_in[13];
    float* out = (float*)d_out;

    float *nx1, *nx2, *q, *k, *v, *ap, *attn;
    cudaGetSymbolAddress((void**)&nx1, g_nx1);
    cudaGetSymbolAddress((void**)&nx2, g_nx2);
    cudaGetSymbolAddress((void**)&q,   g_q);
    cudaGetSymbolAddress((void**)&k,   g_k);
    cudaGetSymbolAddress((void**)&v,   g_v);
    cudaGetSymbolAddress((void**)&ap,  g_ap);
    cudaGetSymbolAddress((void**)&attn, g_attn);

    static bool attr_set = false;
    if (!attr_set) {
        cudaFuncSetAttribute(gemm_tf32, cudaFuncAttributeMaxDynamicSharedMemorySize,
                             STAGES * STG_FLOATS * sizeof(float));
        attr_set = true;
    }
    const size_t gsm = STAGES * STG_FLOATS * sizeof(float);

    // LayerNorms
    ln_kernel<<<B_ * T_, 256>>>(x1, g1, b1, nx1, D_);
    ln_kernel<<<B_ * N_, 256>>>(x2, g2, b2, nx2, L_);

    // Q = nx1 @ Wq ; softmax(+bq) per head
    gemm_tf32<<<dim3(D_ / 128, (B_ * T_) / 128), 256, gsm>>>(nx1, Wq, q, B_ * T_, D_, D_);
    softmax64_kernel<<<B_ * T_, 512>>>(q, bq);

    // K = nx2 @ Wk ; softmax(+bk) per head
    gemm_tf32<<<dim3(D_ / 128, (B_ * N_) / 128), 256, gsm>>>(nx2, Wk, k, B_ * N_, D_, L_);
    softmax64_kernel<<<B_ * N_, 512>>>(k, bk);

    // V = nx2 @ Wv + bv
    gemm_tf32<<<dim3(D_ / 128, (B_ * N_) / 128), 256, gsm>>>(nx2, Wv, v, B_ * N_, D_, L_);
    addbias_kernel<<<B_ * N_, 256>>>(v, bv);

    // attn = k^T v per (b,h): split-N partials then deterministic reduce
    attn_part_kernel<<<dim3(B_ * H_, NSEG), 256>>>(k, v, ap);
    attn_reduce_kernel<<<256, 256>>>(ap, attn);

    // out = x1 @ Wh, then += bh + q @ attn
    gemm_tf32<<<dim3(D_ / 128, (B_ * T_) / 128), 256, gsm>>>(x1, Wh, out, B_ * T_, D_, D_);
    final_kernel<<<dim3(T_ / 64, H_, B_), 256>>>(out, bh, q, attn, out);
}

// round 5
// speedup vs baseline: 1.0914x; 1.0914x over previous
#include <cuda_runtime.h>
#include <cstdint>
#include <mma.h>

using namespace nvcuda;

#define B_  4
#define T_  4096
#define D_  1024
#define N_  2048
#define L_  768
#define H_  16
#define DH  64
#define NSEG 8
#define STAGES 3

// ---------------- scratch (static device globals; no allocation) ----------------
__device__ float g_nx1[(size_t)B_ * T_ * D_];
__device__ float g_nx2[(size_t)B_ * N_ * L_];
__device__ float g_q  [(size_t)B_ * T_ * D_];
__device__ float g_k  [(size_t)B_ * N_ * D_];
__device__ float g_v  [(size_t)B_ * N_ * D_];
__device__ float g_ap [(size_t)NSEG * B_ * H_ * DH * DH];
__device__ float g_attn[(size_t)B_ * H_ * DH * DH];

// ---------------- LayerNorm ----------------
__global__ void __launch_bounds__(256) ln_kernel(const float* __restrict__ x,
                                                 const float* __restrict__ g,
                                                 const float* __restrict__ bb,
                                                 float* __restrict__ out, int D) {
    int row = blockIdx.x;
    const float* xr = x + (size_t)row * D;
    int cnt = D >> 8;
    float v[4];
    float s = 0.f, s2 = 0.f;
    for (int i = 0; i < cnt; i++) {
        v[i] = xr[threadIdx.x + (i << 8)];
        s += v[i];
        s2 += v[i] * v[i];
    }
    #pragma unroll
    for (int o = 16; o; o >>= 1) {
        s  += __shfl_xor_sync(0xffffffffu, s, o);
        s2 += __shfl_xor_sync(0xffffffffu, s2, o);
    }
    __shared__ float sa[8], sb[8];
    int w = threadIdx.x >> 5, lane = threadIdx.x & 31;
    if (lane == 0) { sa[w] = s; sb[w] = s2; }
    __syncthreads();
    if (w == 0) {
        s  = (lane < 8) ? sa[lane] : 0.f;
        s2 = (lane < 8) ? sb[lane] : 0.f;
        #pragma unroll
        for (int o = 4; o; o >>= 1) {
            s  += __shfl_xor_sync(0xffffffffu, s, o);
            s2 += __shfl_xor_sync(0xffffffffu, s2, o);
        }
        if (lane == 0) { sa[0] = s; sb[0] = s2; }
    }
    __syncthreads();
    float invD = 1.f / (float)D;
    float mu  = sa[0] * invD;
    float var = sb[0] * invD - mu * mu;
    float inv = rsqrtf(var + 1e-5f);
    float* orow = out + (size_t)row * D;
    for (int i = 0; i < cnt; i++) {
        int c = threadIdx.x + (i << 8);
        orow[c] = (v[i] - mu) * inv * g[c] + bb[c];
    }
}

// ---------------- cp.async helpers ----------------
__device__ __forceinline__ void cp16(float* smem_dst, const float* gsrc) {
    unsigned int s = (unsigned int)__cvta_generic_to_shared(smem_dst);
    asm volatile("cp.async.cg.shared.global [%0], [%1], 16;\n" :: "r"(s), "l"(gsrc));
}
__device__ __forceinline__ void cp_commit() {
    asm volatile("cp.async.commit_group;\n" ::);
}
__device__ __forceinline__ void cp_wait1() {
    asm volatile("cp.async.wait_group 1;\n" ::);
}

// ---------------- GEMM: C[M,N] = A[M,K] @ W[K,N], tf32 wmma, 3-stage cp.async ----------------
// BM=128 BN=128 BK=32, 256 threads (8 warps in 2x4), warp tile 64x32.
// Per-stage smem: A 128x36 floats (18432B) + B 32x132 floats (16896B) = 35328B; x3 = 105984B.
// 2 CTAs/SM: smem 212KB < 227KB, regs capped to 128 via launch_bounds.
#define A_PITCH 36
#define B_PITCH 132
#define STG_FLOATS 8832   // 128*36 + 32*132

__global__ void __launch_bounds__(256, 2) gemm_tf32(const float* __restrict__ A,
                                                    const float* __restrict__ W,
                                                    float* __restrict__ C,
                                                    int M, int N, int K) {
    extern __shared__ float sm[];
    int bm = blockIdx.y * 128, bn = blockIdx.x * 128;
    int tid = threadIdx.x;
    int wid = tid >> 5;
    int wm = (wid >> 2) * 64, wn = (wid & 3) * 32;

    int ar = tid >> 3,  ac = (tid & 7) << 2;     // A: 32 rows per 256-thread pass
    int br = tid >> 5,  bc = (tid & 31) << 2;    // B: 8 rows per pass

    wmma::fragment<wmma::accumulator, 16, 16, 8, float> acc[4][2];
    #pragma unroll
    for (int i = 0; i < 4; i++)
        #pragma unroll
        for (int j = 0; j < 2; j++) wmma::fill_fragment(acc[i][j], 0.f);

    int KT = K >> 5;

    // prologue: issue STAGES-1 stages
    #pragma unroll
    for (int s = 0; s < STAGES - 1; s++) {
        float* as = sm + s * STG_FLOATS;
        float* bs = as + 128 * A_PITCH;
        int k0 = s << 5;
        #pragma unroll
        for (int i = 0; i < 4; i++) {
            int r = ar + i * 32;
            cp16(as + r * A_PITCH + ac, A + (size_t)(bm + r) * K + k0 + ac);
        }
        #pragma unroll
        for (int i = 0; i < 4; i++) {
            int r = br + i * 8;
            cp16(bs + r * B_PITCH + bc, W + (size_t)(k0 + r) * N + bn + bc);
        }
        cp_commit();
    }

    for (int kt = 0; kt < KT; kt++) {
        cp_wait1();
        __syncthreads();

        int ldk = kt + STAGES - 1;
        if (ldk < KT) {
            int s = ldk % STAGES;
            float* as = sm + s * STG_FLOATS;
            float* bs = as + 128 * A_PITCH;
            int k0 = ldk << 5;
            #pragma unroll
            for (int i = 0; i < 4; i++) {
                int r = ar + i * 32;
                cp16(as + r * A_PITCH + ac, A + (size_t)(bm + r) * K + k0 + ac);
            }
            #pragma unroll
            for (int i = 0; i < 4; i++) {
                int r = br + i * 8;
                cp16(bs + r * B_PITCH + bc, W + (size_t)(k0 + r) * N + bn + bc);
            }
        }
        cp_commit();

        int s = kt % STAGES;
        float* as = sm + s * STG_FLOATS;
        float* bs = as + 128 * A_PITCH;
        #pragma unroll
        for (int kk = 0; kk < 32; kk += 8) {
            wmma::fragment<wmma::matrix_a, 16, 16, 8, wmma::precision::tf32, wmma::row_major> af[4];
            wmma::fragment<wmma::matrix_b, 16, 16, 8, wmma::precision::tf32, wmma::row_major> bf[2];
            #pragma unroll
            for (int i = 0; i < 4; i++) {
                wmma::load_matrix_sync(af[i], as + (wm + 16 * i) * A_PITCH + kk, A_PITCH);
                #pragma unroll
                for (int t = 0; t < af[i].num_elements; t++)
                    af[i].x[t] = wmma::__float_to_tf32(af[i].x[t]);
            }
            #pragma unroll
            for (int j = 0; j < 2; j++) {
                wmma::load_matrix_sync(bf[j], bs + kk * B_PITCH + wn + 16 * j, B_PITCH);
                #pragma unroll
                for (int t = 0; t < bf[j].num_elements; t++)
                    bf[j].x[t] = wmma::__float_to_tf32(bf[j].x[t]);
            }
            #pragma unroll
            for (int i = 0; i < 4; i++)
                #pragma unroll
                for (int j = 0; j < 2; j++)
                    wmma::mma_sync(acc[i][j], af[i], bf[j], acc[i][j]);
        }
        __syncthreads();
    }

    #pragma unroll
    for (int i = 0; i < 4; i++)
        #pragma unroll
        for (int j = 0; j < 2; j++)
            wmma::store_matrix_sync(C + (size_t)(bm + wm + 16 * i) * N + bn + wn + 16 * j,
                                    acc[i][j], N, wmma::mem_row_major);
}

// ---------------- bias + per-head softmax over 64-chunks (in place) ----------------
__global__ void __launch_bounds__(512) softmax64_kernel(float* __restrict__ buf,
                                                        const float* __restrict__ bias) {
    int row = blockIdx.x;
    int w = threadIdx.x >> 5, lane = threadIdx.x & 31;
    float* p = buf + (size_t)row * 1024 + w * 64;
    float a = p[lane]      + bias[w * 64 + lane];
    float b = p[lane + 32] + bias[w * 64 + lane + 32];
    float m = fmaxf(a, b);
    #pragma unroll
    for (int o = 16; o; o >>= 1) m = fmaxf(m, __shfl_xor_sync(0xffffffffu, m, o));
    float ea = __expf(a - m), eb = __expf(b - m);
    float s = ea + eb;
    #pragma unroll
    for (int o = 16; o; o >>= 1) s += __shfl_xor_sync(0xffffffffu, s, o);
    float inv = 1.f / s;
    p[lane]      = ea * inv;
    p[lane + 32] = eb * inv;
}

// ---------------- bias add (V) ----------------
__global__ void __launch_bounds__(256) addbias_kernel(float* __restrict__ v,
                                                      const float* __restrict__ b) {
    float* p = v + (size_t)blockIdx.x * 1024;
    #pragma unroll
    for (int i = 0; i < 4; i++) {
        int c = threadIdx.x + (i << 8);
        p[c] += b[c];
    }
}

// ---------------- attn partials ----------------
__global__ void __launch_bounds__(256) attn_part_kernel(const float* __restrict__ k,
                                                        const float* __restrict__ v,
                                                        float* __restrict__ ap) {
    __shared__ float ks[32][68], vs[32][68];
    int bh = blockIdx.x;
    int b = bh >> 4, h = bh & 15;
    int seg = blockIdx.y;
    int tid = threadIdx.x;
    int d0 = (tid >> 4) << 2, l0 = (tid & 15) << 2;
    float acc[4][4];
    #pragma unroll
    for (int i = 0; i < 4; i++)
        #pragma unroll
        for (int j = 0; j < 4; j++) acc[i][j] = 0.f;

    const float* kb = k + (size_t)(b * N_) * D_ + h * 64;
    const float* vb = v + (size_t)(b * N_) * D_ + h * 64;
    int nend = seg * 256 + 256;
    for (int n0 = seg * 256; n0 < nend; n0 += 32) {
        #pragma unroll
        for (int i = 0; i < 2; i++) {
            int idx = tid + i * 256;
            int r = idx >> 4, c = (idx & 15) << 2;
            *(float4*)&ks[r][c] = *(const float4*)(kb + (size_t)(n0 + r) * D_ + c);
            *(float4*)&vs[r][c] = *(const float4*)(vb + (size_t)(n0 + r) * D_ + c);
        }
        __syncthreads();
        #pragma unroll 8
        for (int n = 0; n < 32; n++) {
            float kr[4], vr[4];
            #pragma unroll
            for (int i = 0; i < 4; i++) { kr[i] = ks[n][d0 + i]; vr[i] = vs[n][l0 + i]; }
            #pragma unroll
            for (int i = 0; i < 4; i++)
                #pragma unroll
                for (int j = 0; j < 4; j++) acc[i][j] += kr[i] * vr[j];
        }
        __syncthreads();
    }
    float* dst = ap + ((size_t)seg * (B_ * H_) + bh) * 4096;
    #pragma unroll
    for (int i = 0; i < 4; i++)
        #pragma unroll
        for (int j = 0; j < 4; j++) dst[(d0 + i) * 64 + l0 + j] = acc[i][j];
}

__global__ void __launch_bounds__(256) attn_reduce_kernel(const float* __restrict__ ap,
                                                          float* __restrict__ attn) {
    int i = blockIdx.x * blockDim.x + threadIdx.x;
    #pragma unroll
    for (int r = 0; r < 4; r++) {
        int j = i + r * 65536;
        float s = 0.f;
        #pragma unroll
        for (int sg = 0; sg < NSEG; sg++) s += ap[(size_t)sg * (B_ * H_ * 4096) + j];
        attn[j] = s;
    }
}

// ---------------- final: out = Ch + bh + q @ attn ----------------
__global__ void __launch_bounds__(256) final_kernel(const float* __restrict__ Ch,
                                                    const float* __restrict__ bh,
                                                    const float* __restrict__ q,
                                                    const float* __restrict__ attn,
                                                    float* __restrict__ out) {
    __shared__ float sA[64][64];
    __shared__ float sQ[64][68];
    int t0 = blockIdx.x * 64, h = blockIdx.y, b = blockIdx.z;
    int tid = threadIdx.x;
    const float* ap = attn + (size_t)(b * H_ + h) * 4096;
    #pragma unroll
    for (int i = 0; i < 4; i++) {
        int idx = tid + i * 256;
        int r = idx >> 4, c = (idx & 15) << 2;
        *(float4*)&sA[r][c] = *(const float4*)(ap + r * 64 + c);
    }
    #pragma unroll
    for (int i = 0; i < 4; i++) {
        int idx = tid + i * 256;
        int r = idx >> 4, c = (idx & 15) << 2;
        *(float4*)&sQ[r][c] = *(const float4*)(q + (size_t)(b * T_ + t0 + r) * D_ + h * 64 + c);
    }
    __syncthreads();
    int tl = tid >> 2, l0 = (tid & 3) << 4;
    float accv[16];
    #pragma unroll
    for (int j = 0; j < 16; j++) accv[j] = 0.f;
    #pragma unroll 4
    for (int d = 0; d < 64; d++) {
        float qd = sQ[tl][d];
        #pragma unroll
        for (int jj = 0; jj < 4; jj++) {
            float4 a4 = *(const float4*)&sA[d][l0 + jj * 4];
            accv[jj * 4 + 0] += qd * a4.x;
            accv[jj * 4 + 1] += qd * a4.y;
            accv[jj * 4 + 2] += qd * a4.z;
            accv[jj * 4 + 3] += qd * a4.w;
        }
    }
    size_t base = (size_t)(b * T_ + t0 + tl) * D_ + h * 64 + l0;
    #pragma unroll
    for (int j = 0; j < 16; j++)
        out[base + j] = Ch[base + j] + bh[h * 64 + l0 + j] + accv[j];
}

// ---------------- launch ----------------
extern "C" void kernel_launch(void* const* d_in, const int* in_sizes, int n_in,
                              void* d_out, int out_size) {
    const float* x1 = (const float*)d_in[0];
    const float* x2 = (const float*)d_in[1];
    const float* Wq = (const float*)d_in[2];
    const float* bq = (const float*)d_in[3];
    const float* Wk = (const float*)d_in[4];
    const float* bk = (const float*)d_in[5];
    const float* Wv = (const float*)d_in[6];
    const float* bv = (const float*)d_in[7];
    const float* Wh = (const float*)d_in[8];
    const float* bh = (const float*)d_in[9];
    const float* g1 = (const float*)d_in[10];
    const float* b1 = (const float*)d_in[11];
    const float* g2 = (const float*)d_in[12];
    const float* b2 = (const float*)d_in[13];
    float* out = (float*)d_out;

    float *nx1, *nx2, *q, *k, *v, *ap, *attn;
    cudaGetSymbolAddress((void**)&nx1, g_nx1);
    cudaGetSymbolAddress((void**)&nx2, g_nx2);
    cudaGetSymbolAddress((void**)&q,   g_q);
    cudaGetSymbolAddress((void**)&k,   g_k);
    cudaGetSymbolAddress((void**)&v,   g_v);
    cudaGetSymbolAddress((void**)&ap,  g_ap);
    cudaGetSymbolAddress((void**)&attn, g_attn);

    static bool attr_set = false;
    if (!attr_set) {
        cudaFuncSetAttribute(gemm_tf32, cudaFuncAttributeMaxDynamicSharedMemorySize,
                             STAGES * STG_FLOATS * sizeof(float));
        attr_set = true;
    }
    const size_t gsm = STAGES * STG_FLOATS * sizeof(float);

    // LayerNorms
    ln_kernel<<<B_ * T_, 256>>>(x1, g1, b1, nx1, D_);
    ln_kernel<<<B_ * N_, 256>>>(x2, g2, b2, nx2, L_);

    // Q = nx1 @ Wq ; softmax(+bq) per head
    gemm_tf32<<<dim3(D_ / 128, (B_ * T_) / 128), 256, gsm>>>(nx1, Wq, q, B_ * T_, D_, D_);
    softmax64_kernel<<<B_ * T_, 512>>>(q, bq);

    // K = nx2 @ Wk ; softmax(+bk) per head
    gemm_tf32<<<dim3(D_ / 128, (B_ * N_) / 128), 256, gsm>>>(nx2, Wk, k, B_ * N_, D_, L_);
    softmax64_kernel<<<B_ * N_, 512>>>(k, bk);

    // V = nx2 @ Wv + bv
    gemm_tf32<<<dim3(D_ / 128, (B_ * N_) / 128), 256, gsm>>>(nx2, Wv, v, B_ * N_, D_, L_);
    addbias_kernel<<<B_ * N_, 256>>>(v, bv);

    // attn = k^T v per (b,h): split-N partials then deterministic reduce
    attn_part_kernel<<<dim3(B_ * H_, NSEG), 256>>>(k, v, ap);
    attn_reduce_kernel<<<256, 256>>>(ap, attn);

    // out = x1 @ Wh, then += bh + q @ attn
    gemm_tf32<<<dim3(D_ / 128, (B_ * T_) / 128), 256, gsm>>>(x1, Wh, out, B_ * T_, D_, D_);
    final_kernel<<<dim3(T_ / 64, H_, B_), 256>>>(out, bh, q, attn, out);
}

// round 9
// speedup vs baseline: 1.1260x; 1.0317x over previous
#include <cuda_runtime.h>
#include <cstdint>
#include <mma.h>

using namespace nvcuda;

#define B_  4
#define T_  4096
#define D_  1024
#define N_  2048
#define L_  768
#define H_  16
#define DH  64
#define NSEG 8
#define STAGES 3

// ---------------- scratch (static device globals; no allocation) ----------------
__device__ float g_nx1[(size_t)B_ * T_ * D_];
__device__ float g_nx2[(size_t)B_ * N_ * L_];
__device__ float g_q  [(size_t)B_ * T_ * D_];
__device__ float g_k  [(size_t)B_ * N_ * D_];
__device__ float g_v  [(size_t)B_ * N_ * D_];
__device__ float g_ap [(size_t)NSEG * B_ * H_ * DH * DH];
__device__ float g_attn[(size_t)B_ * H_ * DH * DH];
__device__ float g_wq[(size_t)D_ * D_];     // tf32-rounded weights (layout unchanged [K,N])
__device__ float g_wk[(size_t)L_ * D_];
__device__ float g_wv[(size_t)L_ * D_];
__device__ float g_wh[(size_t)D_ * D_];
__device__ float g_x1r[(size_t)B_ * T_ * D_]; // tf32-rounded x1

// ---------------- helpers ----------------
__device__ __forceinline__ float to_tf32(float x) {
    float r;
    asm("cvt.rna.tf32.f32 %0, %1;" : "=f"(r) : "f"(x));
    return r;
}
__device__ __forceinline__ void cp16(float* smem_dst, const float* gsrc) {
    unsigned int s = (unsigned int)__cvta_generic_to_shared(smem_dst);
    asm volatile("cp.async.cg.shared.global [%0], [%1], 16;" :: "r"(s), "l"(gsrc));
}
__device__ __forceinline__ void cp_commit() { asm volatile("cp.async.commit_group;" ::); }
__device__ __forceinline__ void cp_wait1()  { asm volatile("cp.async.wait_group 1;" ::); }

// ---------------- elementwise tf32 rounding copy ----------------
__global__ void __launch_bounds__(256) round_tf32_kernel(const float* __restrict__ src,
                                                         float* __restrict__ dst) {
    size_t i = ((size_t)blockIdx.x * 256 + threadIdx.x) * 4;
    float4 t = *(const float4*)(src + i);
    t.x = to_tf32(t.x); t.y = to_tf32(t.y); t.z = to_tf32(t.z); t.w = to_tf32(t.w);
    *(float4*)(dst + i) = t;
}

// ---------------- LayerNorm (emits tf32-rounded output) ----------------
__global__ void __launch_bounds__(256) ln_kernel(const float* __restrict__ x,
                                                 const float* __restrict__ g,
                                                 const float* __restrict__ bb,
                                                 float* __restrict__ out, int D) {
    int row = blockIdx.x;
    const float* xr = x + (size_t)row * D;
    int cnt = D >> 8;
    float v[4];
    float s = 0.f, s2 = 0.f;
    for (int i = 0; i < cnt; i++) {
        v[i] = xr[threadIdx.x + (i << 8)];
        s += v[i];
        s2 += v[i] * v[i];
    }
    #pragma unroll
    for (int o = 16; o; o >>= 1) {
        s  += __shfl_xor_sync(0xffffffffu, s, o);
        s2 += __shfl_xor_sync(0xffffffffu, s2, o);
    }
    __shared__ float sa[8], sb[8];
    int w = threadIdx.x >> 5, lane = threadIdx.x & 31;
    if (lane == 0) { sa[w] = s; sb[w] = s2; }
    __syncthreads();
    if (w == 0) {
        s  = (lane < 8) ? sa[lane] : 0.f;
        s2 = (lane < 8) ? sb[lane] : 0.f;
        #pragma unroll
        for (int o = 4; o; o >>= 1) {
            s  += __shfl_xor_sync(0xffffffffu, s, o);
            s2 += __shfl_xor_sync(0xffffffffu, s2, o);
        }
        if (lane == 0) { sa[0] = s; sb[0] = s2; }
    }
    __syncthreads();
    float invD = 1.f / (float)D;
    float mu  = sa[0] * invD;
    float var = sb[0] * invD - mu * mu;
    float inv = rsqrtf(var + 1e-5f);
    float* orow = out + (size_t)row * D;
    for (int i = 0; i < cnt; i++) {
        int c = threadIdx.x + (i << 8);
        orow[c] = to_tf32((v[i] - mu) * inv * g[c] + bb[c]);
    }
}

// ---------------- GEMM: C[M,N] = A[M,K] @ W[K,N], tf32 wmma, 3-stage cp.async ----------------
// BM=128 BN=256 BK=32, 256 threads (8 warps in 2x4), warp tile 64x64.
// Inputs pre-rounded to tf32: no conversions in the kernel.
// Per-stage smem: A 128x36 (18432B) + B 32x264 (33792B) = 52224B; x3 = 156672B -> 1 CTA/SM.
#define A_PITCH 36
#define B_PITCH 264
#define STG_FLOATS 13056   // 128*36 + 32*264

__global__ void __launch_bounds__(256) gemm_tf32(const float* __restrict__ A,
                                                 const float* __restrict__ W,
                                                 float* __restrict__ C,
                                                 int M, int N, int K) {
    extern __shared__ float sm[];
    int bm = blockIdx.y * 128, bn = blockIdx.x * 256;
    int tid = threadIdx.x;
    int wid = tid >> 5;
    int wm = (wid >> 2) * 64, wn = (wid & 3) * 64;

    int ar = tid >> 3,  ac = (tid & 7) << 2;     // A: 1024 vec4 slots, 32 rows/pass... r=idx>>3
    int br = tid >> 6,  bc = (tid & 63) << 2;    // B: 64 vec4 per row, 4 rows/pass

    wmma::fragment<wmma::accumulator, 16, 16, 8, float> acc[4][4];
    #pragma unroll
    for (int i = 0; i < 4; i++)
        #pragma unroll
        for (int j = 0; j < 4; j++) wmma::fill_fragment(acc[i][j], 0.f);

    int KT = K >> 5;

    // prologue
    #pragma unroll
    for (int s = 0; s < STAGES - 1; s++) {
        float* as = sm + s * STG_FLOATS;
        float* bs = as + 128 * A_PITCH;
        int k0 = s << 5;
        #pragma unroll
        for (int i = 0; i < 4; i++) {
            int r = ar + i * 32;
            cp16(as + r * A_PITCH + ac, A + (size_t)(bm + r) * K + k0 + ac);
        }
        #pragma unroll
        for (int i = 0; i < 8; i++) {
            int r = br + i * 4;
            cp16(bs + r * B_PITCH + bc, W + (size_t)(k0 + r) * N + bn + bc);
        }
        cp_commit();
    }

    for (int kt = 0; kt < KT; kt++) {
        cp_wait1();
        __syncthreads();

        int ldk = kt + STAGES - 1;
        if (ldk < KT) {
            int s = ldk % STAGES;
            float* as = sm + s * STG_FLOATS;
            float* bs = as + 128 * A_PITCH;
            int k0 = ldk << 5;
            #pragma unroll
            for (int i = 0; i < 4; i++) {
                int r = ar + i * 32;
                cp16(as + r * A_PITCH + ac, A + (size_t)(bm + r) * K + k0 + ac);
            }
            #pragma unroll
            for (int i = 0; i < 8; i++) {
                int r = br + i * 4;
                cp16(bs + r * B_PITCH + bc, W + (size_t)(k0 + r) * N + bn + bc);
            }
        }
        cp_commit();

        int s = kt % STAGES;
        float* as = sm + s * STG_FLOATS;
        float* bs = as + 128 * A_PITCH;
        #pragma unroll
        for (int kk = 0; kk < 32; kk += 8) {
            wmma::fragment<wmma::matrix_a, 16, 16, 8, wmma::precision::tf32, wmma::row_major> af[4];
            wmma::fragment<wmma::matrix_b, 16, 16, 8, wmma::precision::tf32, wmma::row_major> bf[4];
            #pragma unroll
            for (int i = 0; i < 4; i++)
                wmma::load_matrix_sync(af[i], as + (wm + 16 * i) * A_PITCH + kk, A_PITCH);
            #pragma unroll
            for (int j = 0; j < 4; j++)
                wmma::load_matrix_sync(bf[j], bs + kk * B_PITCH + wn + 16 * j, B_PITCH);
            #pragma unroll
            for (int i = 0; i < 4; i++)
                #pragma unroll
                for (int j = 0; j < 4; j++)
                    wmma::mma_sync(acc[i][j], af[i], bf[j], acc[i][j]);
        }
        __syncthreads();
    }

    #pragma unroll
    for (int i = 0; i < 4; i++)
        #pragma unroll
        for (int j = 0; j < 4; j++)
            wmma::store_matrix_sync(C + (size_t)(bm + wm + 16 * i) * N + bn + wn + 16 * j,
                                    acc[i][j], N, wmma::mem_row_major);
}

// ---------------- bias + per-head softmax over 64-chunks (in place) ----------------
__global__ void __launch_bounds__(512) softmax64_kernel(float* __restrict__ buf,
                                                        const float* __restrict__ bias) {
    int row = blockIdx.x;
    int w = threadIdx.x >> 5, lane = threadIdx.x & 31;
    float* p = buf + (size_t)row * 1024 + w * 64;
    float a = p[lane]      + bias[w * 64 + lane];
    float b = p[lane + 32] + bias[w * 64 + lane + 32];
    float m = fmaxf(a, b);
    #pragma unroll
    for (int o = 16; o; o >>= 1) m = fmaxf(m, __shfl_xor_sync(0xffffffffu, m, o));
    float ea = __expf(a - m), eb = __expf(b - m);
    float s = ea + eb;
    #pragma unroll
    for (int o = 16; o; o >>= 1) s += __shfl_xor_sync(0xffffffffu, s, o);
    float inv = 1.f / s;
    p[lane]      = ea * inv;
    p[lane + 32] = eb * inv;
}

// ---------------- bias add (V) ----------------
__global__ void __launch_bounds__(256) addbias_kernel(float* __restrict__ v,
                                                      const float* __restrict__ b) {
    float* p = v + (size_t)blockIdx.x * 1024;
    #pragma unroll
    for (int i = 0; i < 4; i++) {
        int c = threadIdx.x + (i << 8);
        p[c] += b[c];
    }
}

// ---------------- attn partials ----------------
__global__ void __launch_bounds__(256) attn_part_kernel(const float* __restrict__ k,
                                                        const float* __restrict__ v,
                                                        float* __restrict__ ap) {
    __shared__ float ks[32][68], vs[32][68];
    int bh = blockIdx.x;
    int b = bh >> 4, h = bh & 15;
    int seg = blockIdx.y;
    int tid = threadIdx.x;
    int d0 = (tid >> 4) << 2, l0 = (tid & 15) << 2;
    float acc[4][4];
    #pragma unroll
    for (int i = 0; i < 4; i++)
        #pragma unroll
        for (int j = 0; j < 4; j++) acc[i][j] = 0.f;

    const float* kb = k + (size_t)(b * N_) * D_ + h * 64;
    const float* vb = v + (size_t)(b * N_) * D_ + h * 64;
    int nend = seg * 256 + 256;
    for (int n0 = seg * 256; n0 < nend; n0 += 32) {
        #pragma unroll
        for (int i = 0; i < 2; i++) {
            int idx = tid + i * 256;
            int r = idx >> 4, c = (idx & 15) << 2;
            *(float4*)&ks[r][c] = *(const float4*)(kb + (size_t)(n0 + r) * D_ + c);
            *(float4*)&vs[r][c] = *(const float4*)(vb + (size_t)(n0 + r) * D_ + c);
        }
        __syncthreads();
        #pragma unroll 8
        for (int n = 0; n < 32; n++) {
            float kr[4], vr[4];
            #pragma unroll
            for (int i = 0; i < 4; i++) { kr[i] = ks[n][d0 + i]; vr[i] = vs[n][l0 + i]; }
            #pragma unroll
            for (int i = 0; i < 4; i++)
                #pragma unroll
                for (int j = 0; j < 4; j++) acc[i][j] += kr[i] * vr[j];
        }
        __syncthreads();
    }
    float* dst = ap + ((size_t)seg * (B_ * H_) + bh) * 4096;
    #pragma unroll
    for (int i = 0; i < 4; i++)
        #pragma unroll
        for (int j = 0; j < 4; j++) dst[(d0 + i) * 64 + l0 + j] = acc[i][j];
}

__global__ void __launch_bounds__(256) attn_reduce_kernel(const float* __restrict__ ap,
                                                          float* __restrict__ attn) {
    int i = blockIdx.x * blockDim.x + threadIdx.x;
    #pragma unroll
    for (int r = 0; r < 4; r++) {
        int j = i + r * 65536;
        float s = 0.f;
        #pragma unroll
        for (int sg = 0; sg < NSEG; sg++) s += ap[(size_t)sg * (B_ * H_ * 4096) + j];
        attn[j] = s;
    }
}

// ---------------- final: out = Ch + bh + q @ attn ----------------
__global__ void __launch_bounds__(256) final_kernel(const float* __restrict__ Ch,
                                                    const float* __restrict__ bh,
                                                    const float* __restrict__ q,
                                                    const float* __restrict__ attn,
                                                    float* __restrict__ out) {
    __shared__ float sA[64][64];
    __shared__ float sQ[64][68];
    int t0 = blockIdx.x * 64, h = blockIdx.y, b = blockIdx.z;
    int tid = threadIdx.x;
    const float* ap = attn + (size_t)(b * H_ + h) * 4096;
    #pragma unroll
    for (int i = 0; i < 4; i++) {
        int idx = tid + i * 256;
        int r = idx >> 4, c = (idx & 15) << 2;
        *(float4*)&sA[r][c] = *(const float4*)(ap + r * 64 + c);
    }
    #pragma unroll
    for (int i = 0; i < 4; i++) {
        int idx = tid + i * 256;
        int r = idx >> 4, c = (idx & 15) << 2;
        *(float4*)&sQ[r][c] = *(const float4*)(q + (size_t)(b * T_ + t0 + r) * D_ + h * 64 + c);
    }
    __syncthreads();
    int tl = tid >> 2, l0 = (tid & 3) << 4;
    float accv[16];
    #pragma unroll
    for (int j = 0; j < 16; j++) accv[j] = 0.f;
    #pragma unroll 4
    for (int d = 0; d < 64; d++) {
        float qd = sQ[tl][d];
        #pragma unroll
        for (int jj = 0; jj < 4; jj++) {
            float4 a4 = *(const float4*)&sA[d][l0 + jj * 4];
            accv[jj * 4 + 0] += qd * a4.x;
            accv[jj * 4 + 1] += qd * a4.y;
            accv[jj * 4 + 2] += qd * a4.z;
            accv[jj * 4 + 3] += qd * a4.w;
        }
    }
    size_t base = (size_t)(b * T_ + t0 + tl) * D_ + h * 64 + l0;
    #pragma unroll
    for (int j = 0; j < 16; j++)
        out[base + j] = Ch[base + j] + bh[h * 64 + l0 + j] + accv[j];
}

// ---------------- launch ----------------
extern "C" void kernel_launch(void* const* d_in, const int* in_sizes, int n_in,
                              void* d_out, int out_size) {
    const float* x1 = (const float*)d_in[0];
    const float* x2 = (const float*)d_in[1];
    const float* Wq = (const float*)d_in[2];
    const float* bq = (const float*)d_in[3];
    const float* Wk = (const float*)d_in[4];
    const float* bk = (const float*)d_in[5];
    const float* Wv = (const float*)d_in[6];
    const float* bv = (const float*)d_in[7];
    const float* Wh = (const float*)d_in[8];
    const float* bh = (const float*)d_in[9];
    const float* g1 = (const float*)d_in[10];
    const float* b1 = (const float*)d_in[11];
    const float* g2 = (const float*)d_in[12];
    const float* b2 = (const float*)d_in[13];
    float* out = (float*)d_out;

    float *nx1, *nx2, *q, *k, *v, *ap, *attn, *wq, *wk, *wv, *wh, *x1r;
    cudaGetSymbolAddress((void**)&nx1, g_nx1);
    cudaGetSymbolAddress((void**)&nx2, g_nx2);
    cudaGetSymbolAddress((void**)&q,   g_q);
    cudaGetSymbolAddress((void**)&k,   g_k);
    cudaGetSymbolAddress((void**)&v,   g_v);
    cudaGetSymbolAddress((void**)&ap,  g_ap);
    cudaGetSymbolAddress((void**)&attn, g_attn);
    cudaGetSymbolAddress((void**)&wq,  g_wq);
    cudaGetSymbolAddress((void**)&wk,  g_wk);
    cudaGetSymbolAddress((void**)&wv,  g_wv);
    cudaGetSymbolAddress((void**)&wh,  g_wh);
    cudaGetSymbolAddress((void**)&x1r, g_x1r);

    static bool attr_set = false;
    if (!attr_set) {
        cudaFuncSetAttribute(gemm_tf32, cudaFuncAttributeMaxDynamicSharedMemorySize,
                             STAGES * STG_FLOATS * sizeof(float));
        attr_set = true;
    }
    const size_t gsm = STAGES * STG_FLOATS * sizeof(float);

    // tf32-round weights + x1 into scratch (GEMM kernel does no conversions)
    round_tf32_kernel<<<(D_ * D_) / 1024, 256>>>(Wq, wq);
    round_tf32_kernel<<<(L_ * D_) / 1024, 256>>>(Wk, wk);
    round_tf32_kernel<<<(L_ * D_) / 1024, 256>>>(Wv, wv);
    round_tf32_kernel<<<(D_ * D_) / 1024, 256>>>(Wh, wh);
    round_tf32_kernel<<<(B_ * T_ * D_) / 1024, 256>>>(x1, x1r);

    // LayerNorms (tf32-rounded outputs)
    ln_kernel<<<B_ * T_, 256>>>(x1, g1, b1, nx1, D_);
    ln_kernel<<<B_ * N_, 256>>>(x2, g2, b2, nx2, L_);

    // Q = nx1 @ Wq ; softmax(+bq) per head
    gemm_tf32<<<dim3(D_ / 256, (B_ * T_) / 128), 256, gsm>>>(nx1, wq, q, B_ * T_, D_, D_);
    softmax64_kernel<<<B_ * T_, 512>>>(q, bq);

    // K = nx2 @ Wk ; softmax(+bk) per head
    gemm_tf32<<<dim3(D_ / 256, (B_ * N_) / 128), 256, gsm>>>(nx2, wk, k, B_ * N_, D_, L_);
    softmax64_kernel<<<B_ * N_, 512>>>(k, bk);

    // V = nx2 @ Wv + bv
    gemm_tf32<<<dim3(D_ / 256, (B_ * N_) / 128), 256, gsm>>>(nx2, wv, v, B_ * N_, D_, L_);
    addbias_kernel<<<B_ * N_, 256>>>(v, bv);

    // attn = k^T v per (b,h): split-N partials then deterministic reduce
    attn_part_kernel<<<dim3(B_ * H_, NSEG), 256>>>(k, v, ap);
    attn_reduce_kernel<<<256, 256>>>(ap, attn);

    // out = x1 @ Wh, then += bh + q @ attn
    gemm_tf32<<<dim3(D_ / 256, (B_ * T_) / 128), 256, gsm>>>(x1r, wh, out, B_ * T_, D_, D_);
    final_kernel<<<dim3(T_ / 64, H_, B_), 256>>>(out, bh, q, attn, out);
}

// round 12
// speedup vs baseline: 2.4603x; 2.1849x over previous
#include <cuda_runtime.h>
#include <cstdint>
#include <cuda_fp16.h>
#include <mma.h>

using namespace nvcuda;

#define B_  4
#define T_  4096
#define D_  1024
#define N_  2048
#define L_  768
#define H_  16
#define DH  64
#define NSEG 8
#define STAGES 3

// ---------------- scratch (static device globals; no allocation) ----------------
__device__ __half g_nx1[(size_t)B_ * T_ * D_];
__device__ __half g_nx2[(size_t)B_ * N_ * L_];
__device__ float  g_q  [(size_t)B_ * T_ * D_];
__device__ float  g_k  [(size_t)B_ * N_ * D_];
__device__ float  g_v  [(size_t)B_ * N_ * D_];
__device__ float  g_ap [(size_t)NSEG * B_ * H_ * DH * DH];
__device__ float  g_attn[(size_t)B_ * H_ * DH * DH];
__device__ __half g_wq[(size_t)D_ * D_];
__device__ __half g_wk[(size_t)L_ * D_];
__device__ __half g_wv[(size_t)L_ * D_];
__device__ __half g_wh[(size_t)D_ * D_];
__device__ __half g_x1h[(size_t)B_ * T_ * D_];

// ---------------- helpers ----------------
__device__ __forceinline__ void cp16(__half* smem_dst, const __half* gsrc) {
    unsigned int s = (unsigned int)__cvta_generic_to_shared(smem_dst);
    asm volatile("cp.async.cg.shared.global [%0], [%1], 16;" :: "r"(s), "l"(gsrc));
}
__device__ __forceinline__ void cp_commit() { asm volatile("cp.async.commit_group;" ::); }
__device__ __forceinline__ void cp_wait1()  { asm volatile("cp.async.wait_group 1;" ::); }

// ---------------- float -> half conversion copy ----------------
__global__ void __launch_bounds__(256) tohalf_kernel(const float* __restrict__ src,
                                                     __half* __restrict__ dst) {
    size_t i = ((size_t)blockIdx.x * 256 + threadIdx.x) * 4;
    float4 t = *(const float4*)(src + i);
    __half2 lo = __floats2half2_rn(t.x, t.y);
    __half2 hi = __floats2half2_rn(t.z, t.w);
    *(__half2*)(dst + i)     = lo;
    *(__half2*)(dst + i + 2) = hi;
}

// ---------------- LayerNorm (emits half output) ----------------
__global__ void __launch_bounds__(256) ln_kernel(const float* __restrict__ x,
                                                 const float* __restrict__ g,
                                                 const float* __restrict__ bb,
                                                 __half* __restrict__ out, int D) {
    int row = blockIdx.x;
    const float* xr = x + (size_t)row * D;
    int cnt = D >> 8;
    float v[4];
    float s = 0.f, s2 = 0.f;
    for (int i = 0; i < cnt; i++) {
        v[i] = xr[threadIdx.x + (i << 8)];
        s += v[i];
        s2 += v[i] * v[i];
    }
    #pragma unroll
    for (int o = 16; o; o >>= 1) {
        s  += __shfl_xor_sync(0xffffffffu, s, o);
        s2 += __shfl_xor_sync(0xffffffffu, s2, o);
    }
    __shared__ float sa[8], sb[8];
    int w = threadIdx.x >> 5, lane = threadIdx.x & 31;
    if (lane == 0) { sa[w] = s; sb[w] = s2; }
    __syncthreads();
    if (w == 0) {
        s  = (lane < 8) ? sa[lane] : 0.f;
        s2 = (lane < 8) ? sb[lane] : 0.f;
        #pragma unroll
        for (int o = 4; o; o >>= 1) {
            s  += __shfl_xor_sync(0xffffffffu, s, o);
            s2 += __shfl_xor_sync(0xffffffffu, s2, o);
        }
        if (lane == 0) { sa[0] = s; sb[0] = s2; }
    }
    __syncthreads();
    float invD = 1.f / (float)D;
    float mu  = sa[0] * invD;
    float var = sb[0] * invD - mu * mu;
    float inv = rsqrtf(var + 1e-5f);
    __half* orow = out + (size_t)row * D;
    for (int i = 0; i < cnt; i++) {
        int c = threadIdx.x + (i << 8);
        orow[c] = __float2half_rn((v[i] - mu) * inv * g[c] + bb[c]);
    }
}

// ---------------- GEMM: C[M,N](f32) = A[M,K](f16) @ W[K,N](f16), fp16 wmma ----------------
// BM=128 BN=128 BK=32, 256 threads (8 warps in 2x4), warp tile 64x32, wmma 16x16x16.
// Per-stage smem: A 128x40 halves (10240B) + B 32x136 halves (8704B) = 18944B; x3 = 56832B.
// 2 CTAs/SM (113.7KB smem), regs capped via launch_bounds.
#define A_PITCH 40
#define B_PITCH 136
#define STG_HALVES 9472   // 128*40 + 32*136

__global__ void __launch_bounds__(256, 2) gemm_f16(const __half* __restrict__ A,
                                                   const __half* __restrict__ W,
                                                   float* __restrict__ C,
                                                   int M, int N, int K) {
    extern __shared__ __half sm[];
    int bm = blockIdx.y * 128, bn = blockIdx.x * 128;
    int tid = threadIdx.x;
    int wid = tid >> 5;
    int wm = (wid >> 2) * 64, wn = (wid & 3) * 32;

    wmma::fragment<wmma::accumulator, 16, 16, 16, float> acc[4][2];
    #pragma unroll
    for (int i = 0; i < 4; i++)
        #pragma unroll
        for (int j = 0; j < 2; j++) wmma::fill_fragment(acc[i][j], 0.f);

    int KT = K >> 5;

    // prologue
    #pragma unroll
    for (int s = 0; s < STAGES - 1; s++) {
        __half* as = sm + s * STG_HALVES;
        __half* bs = as + 128 * A_PITCH;
        int k0 = s << 5;
        #pragma unroll
        for (int i = 0; i < 2; i++) {
            int idx = tid + i * 256;                 // A: 512 16B-chunks
            int r = idx >> 2, c = (idx & 3) << 3;
            cp16(as + r * A_PITCH + c, A + (size_t)(bm + r) * K + k0 + c);
        }
        #pragma unroll
        for (int i = 0; i < 2; i++) {
            int idx = tid + i * 256;                 // B: 512 16B-chunks
            int r = idx >> 4, c = (idx & 15) << 3;
            cp16(bs + r * B_PITCH + c, W + (size_t)(k0 + r) * N + bn + c);
        }
        cp_commit();
    }

    for (int kt = 0; kt < KT; kt++) {
        cp_wait1();
        __syncthreads();

        int ldk = kt + STAGES - 1;
        if (ldk < KT) {
            int s = ldk % STAGES;
            __half* as = sm + s * STG_HALVES;
            __half* bs = as + 128 * A_PITCH;
            int k0 = ldk << 5;
            #pragma unroll
            for (int i = 0; i < 2; i++) {
                int idx = tid + i * 256;
                int r = idx >> 2, c = (idx & 3) << 3;
                cp16(as + r * A_PITCH + c, A + (size_t)(bm + r) * K + k0 + c);
            }
            #pragma unroll
            for (int i = 0; i < 2; i++) {
                int idx = tid + i * 256;
                int r = idx >> 4, c = (idx & 15) << 3;
                cp16(bs + r * B_PITCH + c, W + (size_t)(k0 + r) * N + bn + c);
            }
        }
        cp_commit();

        int s = kt % STAGES;
        __half* as = sm + s * STG_HALVES;
        __half* bs = as + 128 * A_PITCH;
        #pragma unroll
        for (int kk = 0; kk < 32; kk += 16) {
            wmma::fragment<wmma::matrix_a, 16, 16, 16, __half, wmma::row_major> af[4];
            wmma::fragment<wmma::matrix_b, 16, 16, 16, __half, wmma::row_major> bf[2];
            #pragma unroll
            for (int i = 0; i < 4; i++)
                wmma::load_matrix_sync(af[i], as + (wm + 16 * i) * A_PITCH + kk, A_PITCH);
            #pragma unroll
            for (int j = 0; j < 2; j++)
                wmma::load_matrix_sync(bf[j], bs + kk * B_PITCH + wn + 16 * j, B_PITCH);
            #pragma unroll
            for (int i = 0; i < 4; i++)
                #pragma unroll
                for (int j = 0; j < 2; j++)
                    wmma::mma_sync(acc[i][j], af[i], bf[j], acc[i][j]);
        }
        __syncthreads();
    }

    #pragma unroll
    for (int i = 0; i < 4; i++)
        #pragma unroll
        for (int j = 0; j < 2; j++)
            wmma::store_matrix_sync(C + (size_t)(bm + wm + 16 * i) * N + bn + wn + 16 * j,
                                    acc[i][j], N, wmma::mem_row_major);
}

// ---------------- bias + per-head softmax over 64-chunks (in place) ----------------
__global__ void __launch_bounds__(512) softmax64_kernel(float* __restrict__ buf,
                                                        const float* __restrict__ bias) {
    int row = blockIdx.x;
    int w = threadIdx.x >> 5, lane = threadIdx.x & 31;
    float* p = buf + (size_t)row * 1024 + w * 64;
    float a = p[lane]      + bias[w * 64 + lane];
    float b = p[lane + 32] + bias[w * 64 + lane + 32];
    float m = fmaxf(a, b);
    #pragma unroll
    for (int o = 16; o; o >>= 1) m = fmaxf(m, __shfl_xor_sync(0xffffffffu, m, o));
    float ea = __expf(a - m), eb = __expf(b - m);
    float s = ea + eb;
    #pragma unroll
    for (int o = 16; o; o >>= 1) s += __shfl_xor_sync(0xffffffffu, s, o);
    float inv = 1.f / s;
    p[lane]      = ea * inv;
    p[lane + 32] = eb * inv;
}

// ---------------- bias add (V) ----------------
__global__ void __launch_bounds__(256) addbias_kernel(float* __restrict__ v,
                                                      const float* __restrict__ b) {
    float* p = v + (size_t)blockIdx.x * 1024;
    #pragma unroll
    for (int i = 0; i < 4; i++) {
        int c = threadIdx.x + (i << 8);
        p[c] += b[c];
    }
}

// ---------------- attn partials ----------------
__global__ void __launch_bounds__(256) attn_part_kernel(const float* __restrict__ k,
                                                        const float* __restrict__ v,
                                                        float* __restrict__ ap) {
    __shared__ float ks[32][68], vs[32][68];
    int bh = blockIdx.x;
    int b = bh >> 4, h = bh & 15;
    int seg = blockIdx.y;
    int tid = threadIdx.x;
    int d0 = (tid >> 4) << 2, l0 = (tid & 15) << 2;
    float acc[4][4];
    #pragma unroll
    for (int i = 0; i < 4; i++)
        #pragma unroll
        for (int j = 0; j < 4; j++) acc[i][j] = 0.f;

    const float* kb = k + (size_t)(b * N_) * D_ + h * 64;
    const float* vb = v + (size_t)(b * N_) * D_ + h * 64;
    int nend = seg * 256 + 256;
    for (int n0 = seg * 256; n0 < nend; n0 += 32) {
        #pragma unroll
        for (int i = 0; i < 2; i++) {
            int idx = tid + i * 256;
            int r = idx >> 4, c = (idx & 15) << 2;
            *(float4*)&ks[r][c] = *(const float4*)(kb + (size_t)(n0 + r) * D_ + c);
            *(float4*)&vs[r][c] = *(const float4*)(vb + (size_t)(n0 + r) * D_ + c);
        }
        __syncthreads();
        #pragma unroll 8
        for (int n = 0; n < 32; n++) {
            float kr[4], vr[4];
            #pragma unroll
            for (int i = 0; i < 4; i++) { kr[i] = ks[n][d0 + i]; vr[i] = vs[n][l0 + i]; }
            #pragma unroll
            for (int i = 0; i < 4; i++)
                #pragma unroll
                for (int j = 0; j < 4; j++) acc[i][j] += kr[i] * vr[j];
        }
        __syncthreads();
    }
    float* dst = ap + ((size_t)seg * (B_ * H_) + bh) * 4096;
    #pragma unroll
    for (int i = 0; i < 4; i++)
        #pragma unroll
        for (int j = 0; j < 4; j++) dst[(d0 + i) * 64 + l0 + j] = acc[i][j];
}

__global__ void __launch_bounds__(256) attn_reduce_kernel(const float* __restrict__ ap,
                                                          float* __restrict__ attn) {
    int i = blockIdx.x * blockDim.x + threadIdx.x;
    #pragma unroll
    for (int r = 0; r < 4; r++) {
        int j = i + r * 65536;
        float s = 0.f;
        #pragma unroll
        for (int sg = 0; sg < NSEG; sg++) s += ap[(size_t)sg * (B_ * H_ * 4096) + j];
        attn[j] = s;
    }
}

// ---------------- final: out = Ch + bh + q @ attn ----------------
__global__ void __launch_bounds__(256) final_kernel(const float* __restrict__ Ch,
                                                    const float* __restrict__ bh,
                                                    const float* __restrict__ q,
                                                    const float* __restrict__ attn,
                                                    float* __restrict__ out) {
    __shared__ float sA[64][64];
    __shared__ float sQ[64][68];
    int t0 = blockIdx.x * 64, h = blockIdx.y, b = blockIdx.z;
    int tid = threadIdx.x;
    const float* ap = attn + (size_t)(b * H_ + h) * 4096;
    #pragma unroll
    for (int i = 0; i < 4; i++) {
        int idx = tid + i * 256;
        int r = idx >> 4, c = (idx & 15) << 2;
        *(float4*)&sA[r][c] = *(const float4*)(ap + r * 64 + c);
    }
    #pragma unroll
    for (int i = 0; i < 4; i++) {
        int idx = tid + i * 256;
        int r = idx >> 4, c = (idx & 15) << 2;
        *(float4*)&sQ[r][c] = *(const float4*)(q + (size_t)(b * T_ + t0 + r) * D_ + h * 64 + c);
    }
    __syncthreads();
    int tl = tid >> 2, l0 = (tid & 3) << 4;
    float accv[16];
    #pragma unroll
    for (int j = 0; j < 16; j++) accv[j] = 0.f;
    #pragma unroll 4
    for (int d = 0; d < 64; d++) {
        float qd = sQ[tl][d];
        #pragma unroll
        for (int jj = 0; jj < 4; jj++) {
            float4 a4 = *(const float4*)&sA[d][l0 + jj * 4];
            accv[jj * 4 + 0] += qd * a4.x;
            accv[jj * 4 + 1] += qd * a4.y;
            accv[jj * 4 + 2] += qd * a4.z;
            accv[jj * 4 + 3] += qd * a4.w;
        }
    }
    size_t base = (size_t)(b * T_ + t0 + tl) * D_ + h * 64 + l0;
    #pragma unroll
    for (int j = 0; j < 16; j++)
        out[base + j] = Ch[base + j] + bh[h * 64 + l0 + j] + accv[j];
}

// ---------------- launch ----------------
extern "C" void kernel_launch(void* const* d_in, const int* in_sizes, int n_in,
                              void* d_out, int out_size) {
    const float* x1 = (const float*)d_in[0];
    const float* x2 = (const float*)d_in[1];
    const float* Wq = (const float*)d_in[2];
    const float* bq = (const float*)d_in[3];
    const float* Wk = (const float*)d_in[4];
    const float* bk = (const float*)d_in[5];
    const float* Wv = (const float*)d_in[6];
    const float* bv = (const float*)d_in[7];
    const float* Wh = (const float*)d_in[8];
    const float* bh = (const float*)d_in[9];
    const float* g1 = (const float*)d_in[10];
    const float* b1 = (const float*)d_in[11];
    const float* g2 = (const float*)d_in[12];
    const float* b2 = (const float*)d_in[13];
    float* out = (float*)d_out;

    __half *nx1, *nx2, *wq, *wk, *wv, *wh, *x1h;
    float *q, *k, *v, *ap, *attn;
    cudaGetSymbolAddress((void**)&nx1, g_nx1);
    cudaGetSymbolAddress((void**)&nx2, g_nx2);
    cudaGetSymbolAddress((void**)&q,   g_q);
    cudaGetSymbolAddress((void**)&k,   g_k);
    cudaGetSymbolAddress((void**)&v,   g_v);
    cudaGetSymbolAddress((void**)&ap,  g_ap);
    cudaGetSymbolAddress((void**)&attn, g_attn);
    cudaGetSymbolAddress((void**)&wq,  g_wq);
    cudaGetSymbolAddress((void**)&wk,  g_wk);
    cudaGetSymbolAddress((void**)&wv,  g_wv);
    cudaGetSymbolAddress((void**)&wh,  g_wh);
    cudaGetSymbolAddress((void**)&x1h, g_x1h);

    static bool attr_set = false;
    if (!attr_set) {
        cudaFuncSetAttribute(gemm_f16, cudaFuncAttributeMaxDynamicSharedMemorySize,
                             STAGES * STG_HALVES * sizeof(__half));
        attr_set = true;
    }
    const size_t gsm = STAGES * STG_HALVES * sizeof(__half);

    // half conversions (weights + x1)
    tohalf_kernel<<<(D_ * D_) / 1024, 256>>>(Wq, wq);
    tohalf_kernel<<<(L_ * D_) / 1024, 256>>>(Wk, wk);
    tohalf_kernel<<<(L_ * D_) / 1024, 256>>>(Wv, wv);
    tohalf_kernel<<<(D_ * D_) / 1024, 256>>>(Wh, wh);
    tohalf_kernel<<<(B_ * T_ * D_) / 1024, 256>>>(x1, x1h);

    // LayerNorms (half outputs)
    ln_kernel<<<B_ * T_, 256>>>(x1, g1, b1, nx1, D_);
    ln_kernel<<<B_ * N_, 256>>>(x2, g2, b2, nx2, L_);

    // Q = nx1 @ Wq ; softmax(+bq) per head
    gemm_f16<<<dim3(D_ / 128, (B_ * T_) / 128), 256, gsm>>>(nx1, wq, q, B_ * T_, D_, D_);
    softmax64_kernel<<<B_ * T_, 512>>>(q, bq);

    // K = nx2 @ Wk ; softmax(+bk) per head
    gemm_f16<<<dim3(D_ / 128, (B_ * N_) / 128), 256, gsm>>>(nx2, wk, k, B_ * N_, D_, L_);
    softmax64_kernel<<<B_ * N_, 512>>>(k, bk);

    // V = nx2 @ Wv + bv
    gemm_f16<<<dim3(D_ / 128, (B_ * N_) / 128), 256, gsm>>>(nx2, wv, v, B_ * N_, D_, L_);
    addbias_kernel<<<B_ * N_, 256>>>(v, bv);

    // attn = k^T v per (b,h): split-N partials then deterministic reduce
    attn_part_kernel<<<dim3(B_ * H_, NSEG), 256>>>(k, v, ap);
    attn_reduce_kernel<<<256, 256>>>(ap, attn);

    // out = x1 @ Wh, then += bh + q @ attn
    gemm_f16<<<dim3(D_ / 128, (B_ * T_) / 128), 256, gsm>>>(x1h, wh, out, B_ * T_, D_, D_);
    final_kernel<<<dim3(T_ / 64, H_, B_), 256>>>(out, bh, q, attn, out);
}